// round 13
// baseline (speedup 1.0000x reference)
#include <cuda_runtime.h>
#include <cuda_fp16.h>
#include <cstdint>

// ---------------- Problem constants ----------------
#define TOK  16384
#define DIM  1024
#define OUTD 4096

// ---------------- GEMM tiling ----------------
#define BM 256
#define BN 128
#define BKH 64                  // K halves per chunk (128 B row)
#define NTHREADS 512
#define NCHUNK (DIM / BKH)      // 16
#define NSTAGE 3

// smem: swizzled 128B rows
#define XS_BYTES (BM * 128)                 // 32768
#define WS_BYTES (BN * 128)                 // 16384
#define STAGE_BYTES (XS_BYTES + WS_BYTES)   // 49152
#define SMEM_TOTAL (NSTAGE * STAGE_BYTES)   // 147456

// ---------------- Device scratch ----------------
__device__ __half g_Xh[TOK * DIM];          // fp16 X (32 MiB)
__device__ __half g_Wth[2][OUTD][DIM];      // fp16 W^T (16 MiB)
__device__ int    g_perm[2 * TOK];          // routed token lists
__device__ int    g_cnt[2];

// ---------------- small helpers ----------------
__device__ __forceinline__ uint32_t smem_u32(const void* p) {
    uint32_t a;
    asm("{ .reg .u64 t; cvta.to.shared.u64 t, %1; cvt.u32.u64 %0, t; }" : "=r"(a) : "l"(p));
    return a;
}
__device__ __forceinline__ void cp16(uint32_t dst, const void* src) {
    asm volatile("cp.async.cg.shared.global [%0], [%1], 16;" :: "r"(dst), "l"(src));
}
#define CP_COMMIT() asm volatile("cp.async.commit_group;" ::: "memory")
#define CP_WAIT(n)  asm volatile("cp.async.wait_group %0;" :: "n"(n) : "memory")

__device__ __forceinline__ void mma16n8k16(float* d, const uint32_t* a, const uint32_t* b) {
    asm volatile(
        "mma.sync.aligned.m16n8k16.row.col.f32.f16.f16.f32 "
        "{%0,%1,%2,%3}, {%4,%5,%6,%7}, {%8,%9}, {%0,%1,%2,%3};"
        : "+f"(d[0]), "+f"(d[1]), "+f"(d[2]), "+f"(d[3])
        : "r"(a[0]), "r"(a[1]), "r"(a[2]), "r"(a[3]), "r"(b[0]), "r"(b[1]));
}
__device__ __forceinline__ void ldsm_x4(uint32_t* r, uint32_t addr) {
    asm volatile("ldmatrix.sync.aligned.m8n8.x4.shared.b16 {%0,%1,%2,%3}, [%4];"
                 : "=r"(r[0]), "=r"(r[1]), "=r"(r[2]), "=r"(r[3]) : "r"(addr));
}

// ---------------- Prep kernels ----------------
__global__ void halve_x(const float4* __restrict__ X) {
    if (blockIdx.x == 0 && threadIdx.x < 2) g_cnt[threadIdx.x] = 0;
    int i = blockIdx.x * blockDim.x + threadIdx.x;
    float4 v = X[i];
    __half2 h0 = __floats2half2_rn(v.x, v.y);
    __half2 h1 = __floats2half2_rn(v.z, v.w);
    uint2 pk;
    pk.x = *(uint32_t*)&h0;
    pk.y = *(uint32_t*)&h1;
    ((uint2*)g_Xh)[i] = pk;
}

__global__ void compact_tokens(const int* __restrict__ tids) {
    int t = blockIdx.x * blockDim.x + threadIdx.x;
    int e = tids[t];
    int lane = threadIdx.x & 31;
    unsigned m1 = __ballot_sync(0xffffffffu, e == 1);
    unsigned me = (e == 1) ? m1 : ~m1;
    int leader = __ffs(me) - 1;
    int base = 0;
    if (lane == leader) base = atomicAdd(&g_cnt[e], __popc(me));
    base = __shfl_sync(0xffffffffu, base, leader);
    int pos = base + __popc(me & ((1u << lane) - 1u));
    g_perm[e * TOK + pos] = t;
}

__global__ void transpose_w(const float* __restrict__ W0, const float* __restrict__ W1) {
    __shared__ float t[64][65];
    const float* __restrict__ W = blockIdx.z ? W1 : W0;
    const int n0 = blockIdx.x * 64, k0 = blockIdx.y * 64;
    const int tid = threadIdx.x;
    const int tx = tid & 15;
    const int ty = tid >> 4;
#pragma unroll
    for (int i = 0; i < 4; i++) {
        int k = ty + 16 * i;
        float4 v = *(const float4*)&W[(size_t)(k0 + k) * OUTD + n0 + tx * 4];
        t[tx * 4 + 0][k] = v.x;
        t[tx * 4 + 1][k] = v.y;
        t[tx * 4 + 2][k] = v.z;
        t[tx * 4 + 3][k] = v.w;
    }
    __syncthreads();
    const int wn = tid >> 3;
    const int wk = tid & 7;
    __half* __restrict__ Wt = &g_Wth[blockIdx.z][0][0];
#pragma unroll
    for (int p = 0; p < 2; p++) {
        int n = wn + 32 * p;
        const float* row = &t[n][wk * 8];
        __half2 h[4];
#pragma unroll
        for (int q = 0; q < 4; q++)
            h[q] = __floats2half2_rn(row[2 * q], row[2 * q + 1]);
        *(uint4*)&Wt[(size_t)(n0 + n) * DIM + k0 + wk * 8] = *(const uint4*)h;
    }
}

// ---------------- Main routed GEMM: 16 warps, 64x32 tile, 3-stage pipe ----------------
__global__ void __launch_bounds__(NTHREADS, 1)
mot_routed_gemm(const float* __restrict__ b0,
                const float* __restrict__ b1,
                float* __restrict__ out)
{
    const int cnt0 = g_cnt[0];
    const int row0 = blockIdx.y * BM;        // unified row space [0, 16384)
    const int col0 = blockIdx.x * BN;
    const int eLo  = (row0 >= cnt0) ? 1 : 0;
    const int eHi  = (row0 + BM - 1 >= cnt0) ? 1 : 0;
    const int npass = 1 + (eLo != eHi);

    extern __shared__ char dynsm[];
    __shared__ int   tokS[BM];
    __shared__ float biasS[2][BN];

    const int tid  = threadIdx.x;
    const int warp = tid >> 5;
    const int lane = tid & 31;
    const int grp  = lane >> 2;              // 0..7
    const int tig  = lane & 3;               // 0..3
    const int warp_m = warp >> 2;            // 0..3 -> rows warp_m*64
    const int warp_n = warp & 3;             // 0..3 -> cols warp_n*32

    // token list (all unified rows valid) + both biases
    if (tid < 256) {
        int r = row0 + tid;
        int e = (r >= cnt0) ? 1 : 0;
        int idx = r - (e ? cnt0 : 0);
        tokS[tid] = g_perm[e * TOK + idx];
        int be = tid >> 7, j = tid & 127;
        biasS[be][j] = (be ? b1 : b0)[col0 + j];
    }
    __syncthreads();

    // ---- cp.async coordinates: 8 threads fill one 128B row ----
    const int lr = tid >> 3;                 // 0..63 (row group base)
    const int lc = tid & 7;                  // 16B chunk within row
    int myTok[4];
#pragma unroll
    for (int j = 0; j < 4; j++) myTok[j] = tokS[lr + 64 * j];

    const uint32_t sm = smem_u32(dynsm);

    // ---- ldmatrix per-thread addressing (stage-independent) ----
    uint32_t rowA[4]; int swA[4];
#pragma unroll
    for (int i = 0; i < 4; i++) {
        int r = warp_m * 64 + i * 16 + (lane & 15);
        rowA[i] = (uint32_t)r * 128;
        swA[i] = r & 7;
    }
    const int hiA = lane >> 4;
    uint32_t rowB[2]; int swB[2];
#pragma unroll
    for (int jp = 0; jp < 2; jp++) {
        int r = warp_n * 32 + jp * 16 + (lane & 7) + ((lane & 16) >> 1);
        rowB[jp] = (uint32_t)r * 128;
        swB[jp] = r & 7;
    }
    const int parB = (lane >> 3) & 1;

    for (int p = 0; p < npass; p++) {
        const int ep = (npass == 2) ? p : eLo;
        const __half* __restrict__ Wtp = &g_Wth[ep][col0][0];

        auto load_stage = [&](int s, int kk) {
            const uint32_t xs = sm + s * STAGE_BYTES;
            const uint32_t ws = xs + XS_BYTES;
#pragma unroll
            for (int j = 0; j < 4; j++) {          // X: 256 rows, 1 chunk/row
                int row = lr + 64 * j;
                cp16(xs + (uint32_t)row * 128 + (uint32_t)((lc ^ (row & 7)) << 4),
                     g_Xh + (size_t)myTok[j] * DIM + kk + lc * 8);
            }
#pragma unroll
            for (int j = 0; j < 2; j++) {          // W: 128 rows
                int row = lr + 64 * j;
                cp16(ws + (uint32_t)row * 128 + (uint32_t)((lc ^ (row & 7)) << 4),
                     Wtp + (size_t)row * DIM + kk + lc * 8);
            }
        };

        // accumulators: 64x32 warp tile = 4 mtiles x 4 ntiles
        float acc[4][4][4];
#pragma unroll
        for (int i = 0; i < 4; i++)
#pragma unroll
            for (int j = 0; j < 4; j++)
#pragma unroll
                for (int q = 0; q < 4; q++) acc[i][j][q] = 0.0f;

        // ---- 3-stage pipeline: wait_group(1) keeps one load in flight ----
        load_stage(0, 0);
        CP_COMMIT();
        load_stage(1, BKH);
        CP_COMMIT();

        int sc = 0;                          // stage of chunk c
        for (int c = 0; c < NCHUNK; c++) {
            // ensure load(c) complete; load(c+1) may still be pending
            if (c + 1 < NCHUNK) { CP_WAIT(1); } else { CP_WAIT(0); }
            __syncthreads();
            if (c + 2 < NCHUNK) {
                int s2 = sc + 2; if (s2 >= NSTAGE) s2 -= NSTAGE;
                load_stage(s2, (c + 2) * BKH);
                CP_COMMIT();
            }

            const uint32_t xs = sm + sc * STAGE_BYTES;
            const uint32_t ws = xs + XS_BYTES;
            if (++sc == NSTAGE) sc = 0;

#pragma unroll
            for (int ks = 0; ks < 4; ks++) {
                uint32_t a[4][4];
#pragma unroll
                for (int i = 0; i < 4; i++)
                    ldsm_x4(a[i], xs + rowA[i] +
                            (uint32_t)((((2 * ks + hiA) ^ swA[i])) << 4));
                uint32_t b[2][4];            // [jp] = {bj_k0, bj_k1, bj1_k0, bj1_k1}
#pragma unroll
                for (int jp = 0; jp < 2; jp++)
                    ldsm_x4(b[jp], ws + rowB[jp] +
                            (uint32_t)((((2 * ks + parB) ^ swB[jp])) << 4));
#pragma unroll
                for (int i = 0; i < 4; i++)
#pragma unroll
                    for (int jp = 0; jp < 2; jp++) {
                        mma16n8k16(acc[i][2 * jp],     a[i], &b[jp][0]);
                        mma16n8k16(acc[i][2 * jp + 1], a[i], &b[jp][2]);
                    }
            }
        }

        // ---- Epilogue: rows in this pass's range, reg -> gmem ----
        int lo = 0, hi = BM;
        if (npass == 2) {
            if (p == 0) hi = cnt0 - row0;
            else        lo = cnt0 - row0;
        }

        float* __restrict__ oute = out + (size_t)ep * TOK * OUTD;
        float* __restrict__ outo = out + (size_t)(1 - ep) * TOK * OUTD;
        const int colbase = col0 + warp_n * 32 + 2 * tig;

        float2 biasv[4];
#pragma unroll
        for (int j = 0; j < 4; j++)
            biasv[j] = *(const float2*)&biasS[ep][warp_n * 32 + j * 8 + 2 * tig];

#pragma unroll
        for (int i = 0; i < 4; i++) {
            const int lr0 = warp_m * 64 + i * 16 + grp;
            const int lr1 = lr0 + 8;
            const bool v0 = (lr0 >= lo) && (lr0 < hi);
            const bool v1 = (lr1 >= lo) && (lr1 < hi);
            const int t0 = tokS[lr0];
            const int t1 = tokS[lr1];
            float* p0e = oute + (size_t)t0 * OUTD + colbase;
            float* p0o = outo + (size_t)t0 * OUTD + colbase;
            float* p1e = oute + (size_t)t1 * OUTD + colbase;
            float* p1o = outo + (size_t)t1 * OUTD + colbase;
            const float2 z = make_float2(0.f, 0.f);
#pragma unroll
            for (int j = 0; j < 4; j++) {
                if (v0) {
                    float2 v = make_float2(acc[i][j][0] + biasv[j].x,
                                           acc[i][j][1] + biasv[j].y);
                    *(float2*)(p0e + j * 8) = v;
                    *(float2*)(p0o + j * 8) = z;
                }
                if (v1) {
                    float2 v = make_float2(acc[i][j][2] + biasv[j].x,
                                           acc[i][j][3] + biasv[j].y);
                    *(float2*)(p1e + j * 8) = v;
                    *(float2*)(p1o + j * 8) = z;
                }
            }
        }
        if (npass == 2 && p == 0) __syncthreads();   // protect smem reuse across passes
    }
}

// ---------------- Launch ----------------
extern "C" void kernel_launch(void* const* d_in, const int* in_sizes, int n_in,
                              void* d_out, int out_size)
{
    const float* X   = (const float*)d_in[0];
    const int*   tid = (const int*)  d_in[1];
    const float* W0  = (const float*)d_in[2];
    const float* b0  = (const float*)d_in[3];
    const float* W1  = (const float*)d_in[4];
    const float* b1  = (const float*)d_in[5];
    float* out = (float*)d_out;

    cudaFuncSetAttribute(mot_routed_gemm,
                         cudaFuncAttributeMaxDynamicSharedMemorySize, SMEM_TOTAL);

    halve_x<<<(TOK * DIM / 4) / 256, 256>>>((const float4*)X);   // also zeroes g_cnt
    compact_tokens<<<TOK / 256, 256>>>(tid);
    transpose_w<<<dim3(OUTD / 64, DIM / 64, 2), 256>>>(W0, W1);

    dim3 grid(OUTD / BN, TOK / BM);          // 32 x 64
    mot_routed_gemm<<<grid, NTHREADS, SMEM_TOTAL>>>(b0, b1, out);
}

// round 14
// speedup vs baseline: 1.6391x; 1.6391x over previous
#include <cuda_runtime.h>
#include <cuda_fp16.h>
#include <cstdint>

// ---------------- Problem constants ----------------
#define TOK  16384
#define DIM  1024
#define OUTD 4096

// ---------------- GEMM tiling ----------------
#define BM 128
#define BN 128
#define BKH 64                  // K halves per chunk (128 B row)
#define NTHREADS 256
#define NCHUNK (DIM / BKH)      // 16

// smem: swizzled 128B rows
#define XS_BYTES (BM * 128)                 // 16384
#define WS_BYTES (BN * 128)                 // 16384
#define STAGE_BYTES (XS_BYTES + WS_BYTES)   // 32768
#define SMEM_TOTAL (2 * STAGE_BYTES)        // 65536  (x2 CTAs = 128KB/SM)

// ---------------- Device scratch ----------------
__device__ __half g_Xh[TOK * DIM];          // fp16 X (32 MiB)
__device__ __half g_Wth[2][OUTD][DIM];      // fp16 W^T (16 MiB)
__device__ int    g_perm[2 * TOK];          // routed token lists
__device__ int    g_cnt[2];

// ---------------- small helpers ----------------
__device__ __forceinline__ uint32_t smem_u32(const void* p) {
    uint32_t a;
    asm("{ .reg .u64 t; cvta.to.shared.u64 t, %1; cvt.u32.u64 %0, t; }" : "=r"(a) : "l"(p));
    return a;
}
__device__ __forceinline__ void cp16(uint32_t dst, const void* src) {
    asm volatile("cp.async.cg.shared.global [%0], [%1], 16;" :: "r"(dst), "l"(src));
}
#define CP_COMMIT() asm volatile("cp.async.commit_group;" ::: "memory")
#define CP_WAIT(n)  asm volatile("cp.async.wait_group %0;" :: "n"(n) : "memory")

__device__ __forceinline__ void mma16n8k16(float* d, const uint32_t* a, const uint32_t* b) {
    asm volatile(
        "mma.sync.aligned.m16n8k16.row.col.f32.f16.f16.f32 "
        "{%0,%1,%2,%3}, {%4,%5,%6,%7}, {%8,%9}, {%0,%1,%2,%3};"
        : "+f"(d[0]), "+f"(d[1]), "+f"(d[2]), "+f"(d[3])
        : "r"(a[0]), "r"(a[1]), "r"(a[2]), "r"(a[3]), "r"(b[0]), "r"(b[1]));
}
__device__ __forceinline__ void ldsm_x4(uint32_t* r, uint32_t addr) {
    asm volatile("ldmatrix.sync.aligned.m8n8.x4.shared.b16 {%0,%1,%2,%3}, [%4];"
                 : "=r"(r[0]), "=r"(r[1]), "=r"(r[2]), "=r"(r[3]) : "r"(addr));
}

// ---------------- Prep kernels ----------------
__global__ void halve_x(const float4* __restrict__ X) {
    if (blockIdx.x == 0 && threadIdx.x < 2) g_cnt[threadIdx.x] = 0;
    int i = blockIdx.x * blockDim.x + threadIdx.x;
    float4 v = X[i];
    __half2 h0 = __floats2half2_rn(v.x, v.y);
    __half2 h1 = __floats2half2_rn(v.z, v.w);
    uint2 pk;
    pk.x = *(uint32_t*)&h0;
    pk.y = *(uint32_t*)&h1;
    ((uint2*)g_Xh)[i] = pk;
}

__global__ void compact_tokens(const int* __restrict__ tids) {
    int t = blockIdx.x * blockDim.x + threadIdx.x;
    int e = tids[t];
    int lane = threadIdx.x & 31;
    unsigned m1 = __ballot_sync(0xffffffffu, e == 1);
    unsigned me = (e == 1) ? m1 : ~m1;
    int leader = __ffs(me) - 1;
    int base = 0;
    if (lane == leader) base = atomicAdd(&g_cnt[e], __popc(me));
    base = __shfl_sync(0xffffffffu, base, leader);
    int pos = base + __popc(me & ((1u << lane) - 1u));
    g_perm[e * TOK + pos] = t;
}

__global__ void transpose_w(const float* __restrict__ W0, const float* __restrict__ W1) {
    __shared__ float t[64][65];
    const float* __restrict__ W = blockIdx.z ? W1 : W0;
    const int n0 = blockIdx.x * 64, k0 = blockIdx.y * 64;
    const int tid = threadIdx.x;
    const int tx = tid & 15;
    const int ty = tid >> 4;
#pragma unroll
    for (int i = 0; i < 4; i++) {
        int k = ty + 16 * i;
        float4 v = *(const float4*)&W[(size_t)(k0 + k) * OUTD + n0 + tx * 4];
        t[tx * 4 + 0][k] = v.x;
        t[tx * 4 + 1][k] = v.y;
        t[tx * 4 + 2][k] = v.z;
        t[tx * 4 + 3][k] = v.w;
    }
    __syncthreads();
    const int wn = tid >> 3;
    const int wk = tid & 7;
    __half* __restrict__ Wt = &g_Wth[blockIdx.z][0][0];
#pragma unroll
    for (int p = 0; p < 2; p++) {
        int n = wn + 32 * p;
        const float* row = &t[n][wk * 8];
        __half2 h[4];
#pragma unroll
        for (int q = 0; q < 4; q++)
            h[q] = __floats2half2_rn(row[2 * q], row[2 * q + 1]);
        *(uint4*)&Wt[(size_t)(n0 + n) * DIM + k0 + wk * 8] = *(const uint4*)h;
    }
}

// ------------- Main routed GEMM: 128x128 CTA, 8 warps, 2 CTAs/SM -------------
__global__ void __launch_bounds__(NTHREADS, 2)
mot_routed_gemm(const float* __restrict__ b0,
                const float* __restrict__ b1,
                float* __restrict__ out)
{
    const int cnt0 = g_cnt[0];
    const int row0 = blockIdx.y * BM;        // unified row space [0, 16384)
    const int col0 = blockIdx.x * BN;
    const int eLo  = (row0 >= cnt0) ? 1 : 0;
    const int eHi  = (row0 + BM - 1 >= cnt0) ? 1 : 0;
    const int npass = 1 + (eLo != eHi);

    extern __shared__ char dynsm[];
    __shared__ int   tokS[BM];
    __shared__ float biasS[2][BN];

    const int tid  = threadIdx.x;
    const int warp = tid >> 5;
    const int lane = tid & 31;
    const int grp  = lane >> 2;              // 0..7
    const int tig  = lane & 3;               // 0..3
    const int warp_m = warp >> 2;            // 0..1 -> rows warp_m*64
    const int warp_n = warp & 3;             // 0..3 -> cols warp_n*32

    // token list (all unified rows valid) + both biases
    {
        if (tid < BM) {
            int r = row0 + tid;
            int e = (r >= cnt0) ? 1 : 0;
            int idx = r - (e ? cnt0 : 0);
            tokS[tid] = g_perm[e * TOK + idx];
        }
        int be = tid >> 7, j = tid & 127;
        biasS[be][j] = (be ? b1 : b0)[col0 + j];
    }
    __syncthreads();

    // ---- cp.async coordinates: 8 threads fill one 128B row ----
    const int lr = tid >> 3;                 // 0..31 (row group base)
    const int lc = tid & 7;                  // 16B chunk within row
    int myTok[4];
#pragma unroll
    for (int j = 0; j < 4; j++) myTok[j] = tokS[lr + 32 * j];

    const uint32_t sm = smem_u32(dynsm);

    // ---- ldmatrix per-thread addressing (stage-independent) ----
    uint32_t rowA[4]; int swA[4];
#pragma unroll
    for (int i = 0; i < 4; i++) {
        int r = warp_m * 64 + i * 16 + (lane & 15);
        rowA[i] = (uint32_t)r * 128;
        swA[i] = r & 7;
    }
    const int hiA = lane >> 4;
    uint32_t rowB[2]; int swB[2];
#pragma unroll
    for (int jp = 0; jp < 2; jp++) {
        int r = warp_n * 32 + jp * 16 + (lane & 7) + ((lane & 16) >> 1);
        rowB[jp] = (uint32_t)r * 128;
        swB[jp] = r & 7;
    }
    const int parB = (lane >> 3) & 1;

    for (int p = 0; p < npass; p++) {
        const int ep = (npass == 2) ? p : eLo;
        const __half* __restrict__ Wtp = &g_Wth[ep][col0][0];

        auto load_stage = [&](int s, int kk) {
            const uint32_t xs = sm + s * STAGE_BYTES;
            const uint32_t ws = xs + XS_BYTES;
#pragma unroll
            for (int j = 0; j < 4; j++) {          // X: 128 rows, 8 chunks/row
                int row = lr + 32 * j;
                cp16(xs + (uint32_t)row * 128 + (uint32_t)((lc ^ (row & 7)) << 4),
                     g_Xh + (size_t)myTok[j] * DIM + kk + lc * 8);
            }
#pragma unroll
            for (int j = 0; j < 4; j++) {          // W: 128 rows
                int row = lr + 32 * j;
                cp16(ws + (uint32_t)row * 128 + (uint32_t)((lc ^ (row & 7)) << 4),
                     Wtp + (size_t)row * DIM + kk + lc * 8);
            }
        };

        // accumulators: 64x32 warp tile = 4 mtiles x 4 ntiles
        float acc[4][4][4];
#pragma unroll
        for (int i = 0; i < 4; i++)
#pragma unroll
            for (int j = 0; j < 4; j++)
#pragma unroll
                for (int q = 0; q < 4; q++) acc[i][j][q] = 0.0f;

        // ---- 2-stage pipeline, ONE barrier per chunk ----
        load_stage(0, 0);
        CP_COMMIT();

        for (int c = 0; c < NCHUNK; c++) {
            CP_WAIT(0);
            __syncthreads();
            if (c + 1 < NCHUNK) {
                load_stage((c + 1) & 1, (c + 1) * BKH);
                CP_COMMIT();
            }

            const uint32_t xs = sm + (c & 1) * STAGE_BYTES;
            const uint32_t ws = xs + XS_BYTES;

#pragma unroll
            for (int ks = 0; ks < 4; ks++) {
                uint32_t a[4][4];
#pragma unroll
                for (int i = 0; i < 4; i++)
                    ldsm_x4(a[i], xs + rowA[i] +
                            (uint32_t)((((2 * ks + hiA) ^ swA[i])) << 4));
                uint32_t b[2][4];            // [jp] = {bj_k0, bj_k1, bj1_k0, bj1_k1}
#pragma unroll
                for (int jp = 0; jp < 2; jp++)
                    ldsm_x4(b[jp], ws + rowB[jp] +
                            (uint32_t)((((2 * ks + parB) ^ swB[jp])) << 4));
#pragma unroll
                for (int i = 0; i < 4; i++)
#pragma unroll
                    for (int jp = 0; jp < 2; jp++) {
                        mma16n8k16(acc[i][2 * jp],     a[i], &b[jp][0]);
                        mma16n8k16(acc[i][2 * jp + 1], a[i], &b[jp][2]);
                    }
            }
        }

        // ---- Epilogue: rows in this pass's range, reg -> gmem ----
        int lo = 0, hi = BM;
        if (npass == 2) {
            if (p == 0) hi = cnt0 - row0;
            else        lo = cnt0 - row0;
        }

        float* __restrict__ oute = out + (size_t)ep * TOK * OUTD;
        float* __restrict__ outo = out + (size_t)(1 - ep) * TOK * OUTD;
        const int colbase = col0 + warp_n * 32 + 2 * tig;

        float2 biasv[4];
#pragma unroll
        for (int j = 0; j < 4; j++)
            biasv[j] = *(const float2*)&biasS[ep][warp_n * 32 + j * 8 + 2 * tig];

#pragma unroll
        for (int i = 0; i < 4; i++) {
            const int lr0 = warp_m * 64 + i * 16 + grp;
            const int lr1 = lr0 + 8;
            const bool v0 = (lr0 >= lo) && (lr0 < hi);
            const bool v1 = (lr1 >= lo) && (lr1 < hi);
            const int t0 = tokS[lr0];
            const int t1 = tokS[lr1];
            float* p0e = oute + (size_t)t0 * OUTD + colbase;
            float* p0o = outo + (size_t)t0 * OUTD + colbase;
            float* p1e = oute + (size_t)t1 * OUTD + colbase;
            float* p1o = outo + (size_t)t1 * OUTD + colbase;
            const float2 z = make_float2(0.f, 0.f);
#pragma unroll
            for (int j = 0; j < 4; j++) {
                if (v0) {
                    float2 v = make_float2(acc[i][j][0] + biasv[j].x,
                                           acc[i][j][1] + biasv[j].y);
                    *(float2*)(p0e + j * 8) = v;
                    *(float2*)(p0o + j * 8) = z;
                }
                if (v1) {
                    float2 v = make_float2(acc[i][j][2] + biasv[j].x,
                                           acc[i][j][3] + biasv[j].y);
                    *(float2*)(p1e + j * 8) = v;
                    *(float2*)(p1o + j * 8) = z;
                }
            }
        }
        if (npass == 2 && p == 0) __syncthreads();   // protect smem reuse across passes
    }
}

// ---------------- Launch ----------------
extern "C" void kernel_launch(void* const* d_in, const int* in_sizes, int n_in,
                              void* d_out, int out_size)
{
    const float* X   = (const float*)d_in[0];
    const int*   tid = (const int*)  d_in[1];
    const float* W0  = (const float*)d_in[2];
    const float* b0  = (const float*)d_in[3];
    const float* W1  = (const float*)d_in[4];
    const float* b1  = (const float*)d_in[5];
    float* out = (float*)d_out;

    cudaFuncSetAttribute(mot_routed_gemm,
                         cudaFuncAttributeMaxDynamicSharedMemorySize, SMEM_TOTAL);

    halve_x<<<(TOK * DIM / 4) / 256, 256>>>((const float4*)X);   // also zeroes g_cnt
    compact_tokens<<<TOK / 256, 256>>>(tid);
    transpose_w<<<dim3(OUTD / 64, DIM / 64, 2), 256>>>(W0, W1);

    dim3 grid(OUTD / BN, TOK / BM);          // 32 x 128 = 4096 CTAs, 2/SM
    mot_routed_gemm<<<grid, NTHREADS, SMEM_TOTAL>>>(b0, b1, out);
}

// round 15
// speedup vs baseline: 1.6549x; 1.0097x over previous
#include <cuda_runtime.h>
#include <cuda_fp16.h>
#include <cstdint>

// ---------------- Problem constants ----------------
#define TOK  16384
#define DIM  1024
#define OUTD 4096

// ---------------- GEMM tiling ----------------
#define BM 128
#define BN 128
#define BKH 64                  // K halves per chunk (128 B row)
#define NTHREADS 128            // 4 warps, warp tile 64x64
#define NCHUNK (DIM / BKH)      // 16

// smem: swizzled 128B rows
#define XS_BYTES (BM * 128)                 // 16384
#define WS_BYTES (BN * 128)                 // 16384
#define STAGE_BYTES (XS_BYTES + WS_BYTES)   // 32768
#define SMEM_TOTAL (2 * STAGE_BYTES)        // 65536  (x2 CTAs = 128KB/SM)

// ---------------- Device scratch ----------------
__device__ __half g_Xh[TOK * DIM];          // fp16 X (32 MiB)
__device__ __half g_Wth[2][OUTD][DIM];      // fp16 W^T (16 MiB)
__device__ int    g_perm[2 * TOK];          // routed token lists
__device__ int    g_cnt[2];

// ---------------- small helpers ----------------
__device__ __forceinline__ uint32_t smem_u32(const void* p) {
    uint32_t a;
    asm("{ .reg .u64 t; cvta.to.shared.u64 t, %1; cvt.u32.u64 %0, t; }" : "=r"(a) : "l"(p));
    return a;
}
__device__ __forceinline__ void cp16(uint32_t dst, const void* src) {
    asm volatile("cp.async.cg.shared.global [%0], [%1], 16;" :: "r"(dst), "l"(src));
}
#define CP_COMMIT() asm volatile("cp.async.commit_group;" ::: "memory")
#define CP_WAIT(n)  asm volatile("cp.async.wait_group %0;" :: "n"(n) : "memory")

__device__ __forceinline__ void mma16n8k16(float* d, const uint32_t* a, const uint32_t* b) {
    asm volatile(
        "mma.sync.aligned.m16n8k16.row.col.f32.f16.f16.f32 "
        "{%0,%1,%2,%3}, {%4,%5,%6,%7}, {%8,%9}, {%0,%1,%2,%3};"
        : "+f"(d[0]), "+f"(d[1]), "+f"(d[2]), "+f"(d[3])
        : "r"(a[0]), "r"(a[1]), "r"(a[2]), "r"(a[3]), "r"(b[0]), "r"(b[1]));
}
__device__ __forceinline__ void ldsm_x4(uint32_t* r, uint32_t addr) {
    asm volatile("ldmatrix.sync.aligned.m8n8.x4.shared.b16 {%0,%1,%2,%3}, [%4];"
                 : "=r"(r[0]), "=r"(r[1]), "=r"(r[2]), "=r"(r[3]) : "r"(addr));
}

// ---------------- Prep kernels ----------------
__global__ void halve_x(const float4* __restrict__ X) {
    if (blockIdx.x == 0 && threadIdx.x < 2) g_cnt[threadIdx.x] = 0;
    int i = blockIdx.x * blockDim.x + threadIdx.x;
    float4 v = X[i];
    __half2 h0 = __floats2half2_rn(v.x, v.y);
    __half2 h1 = __floats2half2_rn(v.z, v.w);
    uint2 pk;
    pk.x = *(uint32_t*)&h0;
    pk.y = *(uint32_t*)&h1;
    ((uint2*)g_Xh)[i] = pk;
}

__global__ void compact_tokens(const int* __restrict__ tids) {
    int t = blockIdx.x * blockDim.x + threadIdx.x;
    int e = tids[t];
    int lane = threadIdx.x & 31;
    unsigned m1 = __ballot_sync(0xffffffffu, e == 1);
    unsigned me = (e == 1) ? m1 : ~m1;
    int leader = __ffs(me) - 1;
    int base = 0;
    if (lane == leader) base = atomicAdd(&g_cnt[e], __popc(me));
    base = __shfl_sync(0xffffffffu, base, leader);
    int pos = base + __popc(me & ((1u << lane) - 1u));
    g_perm[e * TOK + pos] = t;
}

__global__ void transpose_w(const float* __restrict__ W0, const float* __restrict__ W1) {
    __shared__ float t[64][65];
    const float* __restrict__ W = blockIdx.z ? W1 : W0;
    const int n0 = blockIdx.x * 64, k0 = blockIdx.y * 64;
    const int tid = threadIdx.x;
    const int tx = tid & 15;
    const int ty = tid >> 4;
#pragma unroll
    for (int i = 0; i < 4; i++) {
        int k = ty + 16 * i;
        float4 v = *(const float4*)&W[(size_t)(k0 + k) * OUTD + n0 + tx * 4];
        t[tx * 4 + 0][k] = v.x;
        t[tx * 4 + 1][k] = v.y;
        t[tx * 4 + 2][k] = v.z;
        t[tx * 4 + 3][k] = v.w;
    }
    __syncthreads();
    const int wn = tid >> 3;
    const int wk = tid & 7;
    __half* __restrict__ Wt = &g_Wth[blockIdx.z][0][0];
#pragma unroll
    for (int p = 0; p < 2; p++) {
        int n = wn + 32 * p;
        const float* row = &t[n][wk * 8];
        __half2 h[4];
#pragma unroll
        for (int q = 0; q < 4; q++)
            h[q] = __floats2half2_rn(row[2 * q], row[2 * q + 1]);
        *(uint4*)&Wt[(size_t)(n0 + n) * DIM + k0 + wk * 8] = *(const uint4*)h;
    }
}

// ------- Main routed GEMM: 128x128 CTA, 4 warps x (64x64), 2 CTAs/SM -------
__global__ void __launch_bounds__(NTHREADS, 2)
mot_routed_gemm(const float* __restrict__ b0,
                const float* __restrict__ b1,
                float* __restrict__ out)
{
    const int cnt0 = g_cnt[0];
    const int row0 = blockIdx.y * BM;        // unified row space [0, 16384)
    const int col0 = blockIdx.x * BN;
    const int eLo  = (row0 >= cnt0) ? 1 : 0;
    const int eHi  = (row0 + BM - 1 >= cnt0) ? 1 : 0;
    const int npass = 1 + (eLo != eHi);

    extern __shared__ char dynsm[];
    __shared__ int   tokS[BM];
    __shared__ float biasS[2][BN];

    const int tid  = threadIdx.x;
    const int warp = tid >> 5;
    const int lane = tid & 31;
    const int grp  = lane >> 2;              // 0..7
    const int tig  = lane & 3;               // 0..3
    const int warp_m = warp >> 1;            // 0..1 -> rows warp_m*64
    const int warp_n = warp & 1;             // 0..1 -> cols warp_n*64

    // token list (all unified rows valid) + both biases
    {
        int r = row0 + tid;
        int e = (r >= cnt0) ? 1 : 0;
        int idx = r - (e ? cnt0 : 0);
        tokS[tid] = g_perm[e * TOK + idx];
#pragma unroll
        for (int be = 0; be < 2; be++)
            biasS[be][tid] = (be ? b1 : b0)[col0 + tid];
    }
    __syncthreads();

    // ---- cp.async coordinates: 8 threads fill one 128B row ----
    const int lr = tid >> 3;                 // 0..15 (row group base)
    const int lc = tid & 7;                  // 16B chunk within row
    int myTok[8];
#pragma unroll
    for (int j = 0; j < 8; j++) myTok[j] = tokS[lr + 16 * j];

    const uint32_t sm = smem_u32(dynsm);

    // ---- ldmatrix per-thread addressing (stage-independent) ----
    uint32_t rowA[4]; int swA[4];
#pragma unroll
    for (int i = 0; i < 4; i++) {
        int r = warp_m * 64 + i * 16 + (lane & 15);
        rowA[i] = (uint32_t)r * 128;
        swA[i] = r & 7;
    }
    const int hiA = lane >> 4;
    uint32_t rowB[4]; int swB[4];
#pragma unroll
    for (int jp = 0; jp < 4; jp++) {
        int r = warp_n * 64 + jp * 16 + (lane & 7) + ((lane & 16) >> 1);
        rowB[jp] = (uint32_t)r * 128;
        swB[jp] = r & 7;
    }
    const int parB = (lane >> 3) & 1;

    for (int p = 0; p < npass; p++) {
        const int ep = (npass == 2) ? p : eLo;
        const __half* __restrict__ Wtp = &g_Wth[ep][col0][0];

        auto load_stage = [&](int s, int kk) {
            const uint32_t xs = sm + s * STAGE_BYTES;
            const uint32_t ws = xs + XS_BYTES;
#pragma unroll
            for (int j = 0; j < 8; j++) {          // X: 128 rows
                int row = lr + 16 * j;
                cp16(xs + (uint32_t)row * 128 + (uint32_t)((lc ^ (row & 7)) << 4),
                     g_Xh + (size_t)myTok[j] * DIM + kk + lc * 8);
            }
#pragma unroll
            for (int j = 0; j < 8; j++) {          // W: 128 rows
                int row = lr + 16 * j;
                cp16(ws + (uint32_t)row * 128 + (uint32_t)((lc ^ (row & 7)) << 4),
                     Wtp + (size_t)row * DIM + kk + lc * 8);
            }
        };

        // accumulators: 64x64 warp tile = 4 mtiles x 8 ntiles
        float acc[4][8][4];
#pragma unroll
        for (int i = 0; i < 4; i++)
#pragma unroll
            for (int j = 0; j < 8; j++)
#pragma unroll
                for (int q = 0; q < 4; q++) acc[i][j][q] = 0.0f;

        // ---- 2-stage pipeline, ONE barrier per chunk ----
        load_stage(0, 0);
        CP_COMMIT();

        for (int c = 0; c < NCHUNK; c++) {
            CP_WAIT(0);
            __syncthreads();
            if (c + 1 < NCHUNK) {
                load_stage((c + 1) & 1, (c + 1) * BKH);
                CP_COMMIT();
            }

            const uint32_t xs = sm + (c & 1) * STAGE_BYTES;
            const uint32_t ws = xs + XS_BYTES;

#pragma unroll
            for (int ks = 0; ks < 4; ks++) {
                uint32_t a[4][4];
#pragma unroll
                for (int i = 0; i < 4; i++)
                    ldsm_x4(a[i], xs + rowA[i] +
                            (uint32_t)((((2 * ks + hiA) ^ swA[i])) << 4));
                uint32_t b[4][4];            // [jp] = {bj_k0, bj_k1, bj1_k0, bj1_k1}
#pragma unroll
                for (int jp = 0; jp < 4; jp++)
                    ldsm_x4(b[jp], ws + rowB[jp] +
                            (uint32_t)((((2 * ks + parB) ^ swB[jp])) << 4));
#pragma unroll
                for (int i = 0; i < 4; i++)
#pragma unroll
                    for (int jp = 0; jp < 4; jp++) {
                        mma16n8k16(acc[i][2 * jp],     a[i], &b[jp][0]);
                        mma16n8k16(acc[i][2 * jp + 1], a[i], &b[jp][2]);
                    }
            }
        }

        // ---- Epilogue: rows in this pass's range, reg -> gmem ----
        int lo = 0, hi = BM;
        if (npass == 2) {
            if (p == 0) hi = cnt0 - row0;
            else        lo = cnt0 - row0;
        }

        float* __restrict__ oute = out + (size_t)ep * TOK * OUTD;
        float* __restrict__ outo = out + (size_t)(1 - ep) * TOK * OUTD;
        const int colbase = col0 + warp_n * 64 + 2 * tig;

        float2 biasv[8];
#pragma unroll
        for (int j = 0; j < 8; j++)
            biasv[j] = *(const float2*)&biasS[ep][warp_n * 64 + j * 8 + 2 * tig];

#pragma unroll
        for (int i = 0; i < 4; i++) {
            const int lr0 = warp_m * 64 + i * 16 + grp;
            const int lr1 = lr0 + 8;
            const bool v0 = (lr0 >= lo) && (lr0 < hi);
            const bool v1 = (lr1 >= lo) && (lr1 < hi);
            const int t0 = tokS[lr0];
            const int t1 = tokS[lr1];
            float* p0e = oute + (size_t)t0 * OUTD + colbase;
            float* p0o = outo + (size_t)t0 * OUTD + colbase;
            float* p1e = oute + (size_t)t1 * OUTD + colbase;
            float* p1o = outo + (size_t)t1 * OUTD + colbase;
            const float2 z = make_float2(0.f, 0.f);
#pragma unroll
            for (int j = 0; j < 8; j++) {
                if (v0) {
                    float2 v = make_float2(acc[i][j][0] + biasv[j].x,
                                           acc[i][j][1] + biasv[j].y);
                    *(float2*)(p0e + j * 8) = v;
                    *(float2*)(p0o + j * 8) = z;
                }
                if (v1) {
                    float2 v = make_float2(acc[i][j][2] + biasv[j].x,
                                           acc[i][j][3] + biasv[j].y);
                    *(float2*)(p1e + j * 8) = v;
                    *(float2*)(p1o + j * 8) = z;
                }
            }
        }
        if (npass == 2 && p == 0) __syncthreads();   // protect smem reuse across passes
    }
}

// ---------------- Launch ----------------
extern "C" void kernel_launch(void* const* d_in, const int* in_sizes, int n_in,
                              void* d_out, int out_size)
{
    const float* X   = (const float*)d_in[0];
    const int*   tid = (const int*)  d_in[1];
    const float* W0  = (const float*)d_in[2];
    const float* b0  = (const float*)d_in[3];
    const float* W1  = (const float*)d_in[4];
    const float* b1  = (const float*)d_in[5];
    float* out = (float*)d_out;

    cudaFuncSetAttribute(mot_routed_gemm,
                         cudaFuncAttributeMaxDynamicSharedMemorySize, SMEM_TOTAL);

    halve_x<<<(TOK * DIM / 4) / 256, 256>>>((const float4*)X);   // also zeroes g_cnt
    compact_tokens<<<TOK / 256, 256>>>(tid);
    transpose_w<<<dim3(OUTD / 64, DIM / 64, 2), 256>>>(W0, W1);

    dim3 grid(OUTD / BN, TOK / BM);          // 32 x 128 = 4096 CTAs, 2/SM
    mot_routed_gemm<<<grid, NTHREADS, SMEM_TOTAL>>>(b0, b1, out);
}

// round 16
// speedup vs baseline: 1.6753x; 1.0123x over previous
#include <cuda_runtime.h>
#include <cuda_fp16.h>
#include <cstdint>

// ---------------- Problem constants ----------------
#define TOK  16384
#define DIM  1024
#define OUTD 4096

// ---------------- GEMM tiling ----------------
#define BM 128
#define BN 128
#define BKH 64                  // K halves per chunk (128 B row)
#define NTHREADS 128            // 4 warps, warp tile 64x64
#define NCHUNK (DIM / BKH)      // 16
#define NSTAGE 3

// smem: swizzled 128B rows
#define XS_BYTES (BM * 128)                 // 16384
#define WS_BYTES (BN * 128)                 // 16384
#define STAGE_BYTES (XS_BYTES + WS_BYTES)   // 32768
#define SMEM_TOTAL (NSTAGE * STAGE_BYTES)   // 98304  (x2 CTAs = 192KB/SM)

// ---------------- Device scratch ----------------
__device__ __half g_Xh[TOK * DIM];          // fp16 X (32 MiB)
__device__ __half g_Wth[2][OUTD][DIM];      // fp16 W^T (16 MiB)
__device__ int    g_perm[2 * TOK];          // routed token lists
__device__ int    g_cnt[2];

// ---------------- small helpers ----------------
__device__ __forceinline__ uint32_t smem_u32(const void* p) {
    uint32_t a;
    asm("{ .reg .u64 t; cvta.to.shared.u64 t, %1; cvt.u32.u64 %0, t; }" : "=r"(a) : "l"(p));
    return a;
}
__device__ __forceinline__ void cp16(uint32_t dst, const void* src) {
    asm volatile("cp.async.cg.shared.global [%0], [%1], 16;" :: "r"(dst), "l"(src));
}
#define CP_COMMIT() asm volatile("cp.async.commit_group;" ::: "memory")
#define CP_WAIT(n)  asm volatile("cp.async.wait_group %0;" :: "n"(n) : "memory")

__device__ __forceinline__ void mma16n8k16(float* d, const uint32_t* a, const uint32_t* b) {
    asm volatile(
        "mma.sync.aligned.m16n8k16.row.col.f32.f16.f16.f32 "
        "{%0,%1,%2,%3}, {%4,%5,%6,%7}, {%8,%9}, {%0,%1,%2,%3};"
        : "+f"(d[0]), "+f"(d[1]), "+f"(d[2]), "+f"(d[3])
        : "r"(a[0]), "r"(a[1]), "r"(a[2]), "r"(a[3]), "r"(b[0]), "r"(b[1]));
}
__device__ __forceinline__ void ldsm_x4(uint32_t* r, uint32_t addr) {
    asm volatile("ldmatrix.sync.aligned.m8n8.x4.shared.b16 {%0,%1,%2,%3}, [%4];"
                 : "=r"(r[0]), "=r"(r[1]), "=r"(r[2]), "=r"(r[3]) : "r"(addr));
}

// ---------------- Prep kernels ----------------
__global__ void halve_x(const float4* __restrict__ X) {
    if (blockIdx.x == 0 && threadIdx.x < 2) g_cnt[threadIdx.x] = 0;
    int i = blockIdx.x * blockDim.x + threadIdx.x;
    float4 v = X[i];
    __half2 h0 = __floats2half2_rn(v.x, v.y);
    __half2 h1 = __floats2half2_rn(v.z, v.w);
    uint2 pk;
    pk.x = *(uint32_t*)&h0;
    pk.y = *(uint32_t*)&h1;
    ((uint2*)g_Xh)[i] = pk;
}

__global__ void compact_tokens(const int* __restrict__ tids) {
    int t = blockIdx.x * blockDim.x + threadIdx.x;
    int e = tids[t];
    int lane = threadIdx.x & 31;
    unsigned m1 = __ballot_sync(0xffffffffu, e == 1);
    unsigned me = (e == 1) ? m1 : ~m1;
    int leader = __ffs(me) - 1;
    int base = 0;
    if (lane == leader) base = atomicAdd(&g_cnt[e], __popc(me));
    base = __shfl_sync(0xffffffffu, base, leader);
    int pos = base + __popc(me & ((1u << lane) - 1u));
    g_perm[e * TOK + pos] = t;
}

__global__ void transpose_w(const float* __restrict__ W0, const float* __restrict__ W1) {
    __shared__ float t[64][65];
    const float* __restrict__ W = blockIdx.z ? W1 : W0;
    const int n0 = blockIdx.x * 64, k0 = blockIdx.y * 64;
    const int tid = threadIdx.x;
    const int tx = tid & 15;
    const int ty = tid >> 4;
#pragma unroll
    for (int i = 0; i < 4; i++) {
        int k = ty + 16 * i;
        float4 v = *(const float4*)&W[(size_t)(k0 + k) * OUTD + n0 + tx * 4];
        t[tx * 4 + 0][k] = v.x;
        t[tx * 4 + 1][k] = v.y;
        t[tx * 4 + 2][k] = v.z;
        t[tx * 4 + 3][k] = v.w;
    }
    __syncthreads();
    const int wn = tid >> 3;
    const int wk = tid & 7;
    __half* __restrict__ Wt = &g_Wth[blockIdx.z][0][0];
#pragma unroll
    for (int p = 0; p < 2; p++) {
        int n = wn + 32 * p;
        const float* row = &t[n][wk * 8];
        __half2 h[4];
#pragma unroll
        for (int q = 0; q < 4; q++)
            h[q] = __floats2half2_rn(row[2 * q], row[2 * q + 1]);
        *(uint4*)&Wt[(size_t)(n0 + n) * DIM + k0 + wk * 8] = *(const uint4*)h;
    }
}

// -- Main routed GEMM: 128x128 CTA, 4 warps x (64x64), 2 CTAs/SM, 3-stage --
__global__ void __launch_bounds__(NTHREADS, 2)
mot_routed_gemm(const float* __restrict__ b0,
                const float* __restrict__ b1,
                float* __restrict__ out)
{
    const int cnt0 = g_cnt[0];
    const int row0 = blockIdx.y * BM;        // unified row space [0, 16384)
    const int col0 = blockIdx.x * BN;
    const int eLo  = (row0 >= cnt0) ? 1 : 0;
    const int eHi  = (row0 + BM - 1 >= cnt0) ? 1 : 0;
    const int npass = 1 + (eLo != eHi);

    extern __shared__ char dynsm[];
    __shared__ int   tokS[BM];
    __shared__ float biasS[2][BN];

    const int tid  = threadIdx.x;
    const int warp = tid >> 5;
    const int lane = tid & 31;
    const int grp  = lane >> 2;              // 0..7
    const int tig  = lane & 3;               // 0..3
    const int warp_m = warp >> 1;            // 0..1 -> rows warp_m*64
    const int warp_n = warp & 1;             // 0..1 -> cols warp_n*64

    // token list (all unified rows valid) + both biases
    {
        int r = row0 + tid;
        int e = (r >= cnt0) ? 1 : 0;
        int idx = r - (e ? cnt0 : 0);
        tokS[tid] = g_perm[e * TOK + idx];
#pragma unroll
        for (int be = 0; be < 2; be++)
            biasS[be][tid] = (be ? b1 : b0)[col0 + tid];
    }
    __syncthreads();

    // ---- cp.async coordinates: 8 threads fill one 128B row ----
    const int lr = tid >> 3;                 // 0..15 (row group base)
    const int lc = tid & 7;                  // 16B chunk within row
    int myTok[8];
#pragma unroll
    for (int j = 0; j < 8; j++) myTok[j] = tokS[lr + 16 * j];

    const uint32_t sm = smem_u32(dynsm);

    // ---- ldmatrix per-thread addressing (stage-independent) ----
    uint32_t rowA[4]; int swA[4];
#pragma unroll
    for (int i = 0; i < 4; i++) {
        int r = warp_m * 64 + i * 16 + (lane & 15);
        rowA[i] = (uint32_t)r * 128;
        swA[i] = r & 7;
    }
    const int hiA = lane >> 4;
    uint32_t rowB[4]; int swB[4];
#pragma unroll
    for (int jp = 0; jp < 4; jp++) {
        int r = warp_n * 64 + jp * 16 + (lane & 7) + ((lane & 16) >> 1);
        rowB[jp] = (uint32_t)r * 128;
        swB[jp] = r & 7;
    }
    const int parB = (lane >> 3) & 1;

    for (int p = 0; p < npass; p++) {
        const int ep = (npass == 2) ? p : eLo;
        const __half* __restrict__ Wtp = &g_Wth[ep][col0][0];

        auto load_stage = [&](uint32_t xs, int kk) {
            const uint32_t ws = xs + XS_BYTES;
#pragma unroll
            for (int j = 0; j < 8; j++) {          // X: 128 rows
                int row = lr + 16 * j;
                cp16(xs + (uint32_t)row * 128 + (uint32_t)((lc ^ (row & 7)) << 4),
                     g_Xh + (size_t)myTok[j] * DIM + kk + lc * 8);
            }
#pragma unroll
            for (int j = 0; j < 8; j++) {          // W: 128 rows
                int row = lr + 16 * j;
                cp16(ws + (uint32_t)row * 128 + (uint32_t)((lc ^ (row & 7)) << 4),
                     Wtp + (size_t)row * DIM + kk + lc * 8);
            }
        };

        // accumulators: 64x64 warp tile = 4 mtiles x 8 ntiles
        float acc[4][8][4];
#pragma unroll
        for (int i = 0; i < 4; i++)
#pragma unroll
            for (int j = 0; j < 8; j++)
#pragma unroll
                for (int q = 0; q < 4; q++) acc[i][j][q] = 0.0f;

        // ---- 3-stage pipeline, rotating base registers ----
        uint32_t s0 = sm;                        // stage of chunk c (compute)
        uint32_t s1 = sm + STAGE_BYTES;          // stage of chunk c+1 (in flight)
        uint32_t s2 = sm + 2 * STAGE_BYTES;      // stage of chunk c+2 (to issue)

        load_stage(s0, 0);
        CP_COMMIT();
        load_stage(s1, BKH);
        CP_COMMIT();

        for (int c = 0; c < NCHUNK; c++) {
            // chunk c resident; chunk c+1 may still be streaming
            if (c + 1 < NCHUNK) { CP_WAIT(1); } else { CP_WAIT(0); }
            __syncthreads();
            if (c + 2 < NCHUNK) {
                load_stage(s2, (c + 2) * BKH);
                CP_COMMIT();
            }

            const uint32_t xs = s0;
            const uint32_t ws = s0 + XS_BYTES;

#pragma unroll
            for (int ks = 0; ks < 4; ks++) {
                uint32_t a[4][4];
#pragma unroll
                for (int i = 0; i < 4; i++)
                    ldsm_x4(a[i], xs + rowA[i] +
                            (uint32_t)((((2 * ks + hiA) ^ swA[i])) << 4));
                uint32_t b[4][4];            // [jp] = {bj_k0, bj_k1, bj1_k0, bj1_k1}
#pragma unroll
                for (int jp = 0; jp < 4; jp++)
                    ldsm_x4(b[jp], ws + rowB[jp] +
                            (uint32_t)((((2 * ks + parB) ^ swB[jp])) << 4));
#pragma unroll
                for (int i = 0; i < 4; i++)
#pragma unroll
                    for (int jp = 0; jp < 4; jp++) {
                        mma16n8k16(acc[i][2 * jp],     a[i], &b[jp][0]);
                        mma16n8k16(acc[i][2 * jp + 1], a[i], &b[jp][2]);
                    }
            }

            // rotate stages: c+1 becomes compute, c+2 in flight, freed -> issue
            uint32_t tmp = s0; s0 = s1; s1 = s2; s2 = tmp;
        }

        // ---- Epilogue: rows in this pass's range, reg -> gmem ----
        int lo = 0, hi = BM;
        if (npass == 2) {
            if (p == 0) hi = cnt0 - row0;
            else        lo = cnt0 - row0;
        }

        float* __restrict__ oute = out + (size_t)ep * TOK * OUTD;
        float* __restrict__ outo = out + (size_t)(1 - ep) * TOK * OUTD;
        const int colbase = col0 + warp_n * 64 + 2 * tig;

        float2 biasv[8];
#pragma unroll
        for (int j = 0; j < 8; j++)
            biasv[j] = *(const float2*)&biasS[ep][warp_n * 64 + j * 8 + 2 * tig];

#pragma unroll
        for (int i = 0; i < 4; i++) {
            const int lr0 = warp_m * 64 + i * 16 + grp;
            const int lr1 = lr0 + 8;
            const bool v0 = (lr0 >= lo) && (lr0 < hi);
            const bool v1 = (lr1 >= lo) && (lr1 < hi);
            const int t0 = tokS[lr0];
            const int t1 = tokS[lr1];
            float* p0e = oute + (size_t)t0 * OUTD + colbase;
            float* p0o = outo + (size_t)t0 * OUTD + colbase;
            float* p1e = oute + (size_t)t1 * OUTD + colbase;
            float* p1o = outo + (size_t)t1 * OUTD + colbase;
            const float2 z = make_float2(0.f, 0.f);
#pragma unroll
            for (int j = 0; j < 8; j++) {
                if (v0) {
                    float2 v = make_float2(acc[i][j][0] + biasv[j].x,
                                           acc[i][j][1] + biasv[j].y);
                    *(float2*)(p0e + j * 8) = v;
                    *(float2*)(p0o + j * 8) = z;
                }
                if (v1) {
                    float2 v = make_float2(acc[i][j][2] + biasv[j].x,
                                           acc[i][j][3] + biasv[j].y);
                    *(float2*)(p1e + j * 8) = v;
                    *(float2*)(p1o + j * 8) = z;
                }
            }
        }
        if (npass == 2 && p == 0) __syncthreads();   // protect smem reuse across passes
    }
}

// ---------------- Launch ----------------
extern "C" void kernel_launch(void* const* d_in, const int* in_sizes, int n_in,
                              void* d_out, int out_size)
{
    const float* X   = (const float*)d_in[0];
    const int*   tid = (const int*)  d_in[1];
    const float* W0  = (const float*)d_in[2];
    const float* b0  = (const float*)d_in[3];
    const float* W1  = (const float*)d_in[4];
    const float* b1  = (const float*)d_in[5];
    float* out = (float*)d_out;

    cudaFuncSetAttribute(mot_routed_gemm,
                         cudaFuncAttributeMaxDynamicSharedMemorySize, SMEM_TOTAL);

    halve_x<<<(TOK * DIM / 4) / 256, 256>>>((const float4*)X);   // also zeroes g_cnt
    compact_tokens<<<TOK / 256, 256>>>(tid);
    transpose_w<<<dim3(OUTD / 64, DIM / 64, 2), 256>>>(W0, W1);

    dim3 grid(OUTD / BN, TOK / BM);          // 32 x 128 = 4096 CTAs, 2/SM
    mot_routed_gemm<<<grid, NTHREADS, SMEM_TOTAL>>>(b0, b1, out);
}